// round 4
// baseline (speedup 1.0000x reference)
#include <cuda_runtime.h>
#include <cuda_bf16.h>

// InterLayerTrajectoryFlow: fused diff -> normalize -> causal 6-tap weighted sum.
// emb: [B, S, D] fp32, S=8192, D=512.
//
// Register-resident design: block = (batch, 16-position chunk), 512 threads
// (one feature column each). Each thread keeps all 21 diff rows of its column
// in registers. Norms via full warp-shuffle butterfly + tiny smem broadcast.
// Output is pure register FMA against fused (weight * inv-norm * scale) coeffs.

#define S_LEN 8192
#define D_DIM 512
#define PC 16                 // positions per block
#define ER (PC + 6)           // 22 embedding rows (chunk + halo)
#define DR (PC + 5)           // 21 diff rows
#define WIN 6

__global__ __launch_bounds__(512, 3)
void traj_flow_kernel(const float* __restrict__ emb,
                      const int* __restrict__ layer_idx,
                      float* __restrict__ out) {
    __shared__ float spsum[DR * 16 + 8];       // per-warp row sums [DR][16]
    __shared__ float srinv[DR + 3];            // per-diff-row inverse norms
    __shared__ float scw[PC * WIN];            // fused coefficients

    const int col  = threadIdx.x;              // 0..511 = feature column
    const int lane = col & 31;
    const int wid  = col >> 5;
    const int b    = blockIdx.y;
    const int pos0 = blockIdx.x * PC;

    // ---------- Phase 1: load 22 rows, keep 21 diffs in registers ----------
    float diffs[DR];
    {
        const int gr0 = pos0 - WIN;
        const float* ep = emb + ((long long)(b * S_LEN + gr0)) * D_DIM + col;
        float prev = 0.0f, cur;
        if (pos0 == 0) {
            #pragma unroll
            for (int r = 0; r < ER; ++r) {
                cur = (r >= WIN) ? ep[r * D_DIM] : 0.0f;
                if (r > 0) diffs[r - 1] = cur - prev;
                prev = cur;
            }
        } else {
            #pragma unroll
            for (int r = 0; r < ER; ++r) {
                cur = ep[r * D_DIM];
                if (r > 0) diffs[r - 1] = cur - prev;
                prev = cur;
            }
        }
    }

    // ---------- Phase 2a: full butterfly per row -> per-warp sums ----------
    #pragma unroll
    for (int r = 0; r < DR; ++r) {
        float s = diffs[r] * diffs[r];
        #pragma unroll
        for (int o = 16; o > 0; o >>= 1)
            s += __shfl_xor_sync(0xffffffffu, s, o);
        if (lane == 0) spsum[r * 16 + wid] = s;
    }
    __syncthreads();

    // ---------- Phase 2b: combine 16 warp sums per row (16 warps x 21 rows) ----------
    if (wid < DR >= 16 ? (wid < 16) : true) { /* all 16 warps participate */ }
    for (int r = wid; r < DR; r += 16) {
        float s = (lane < 16) ? spsum[r * 16 + lane] : 0.0f;
        #pragma unroll
        for (int o = 8; o > 0; o >>= 1)
            s += __shfl_xor_sync(0xffffffffu, s, o);
        if (lane == 0) {
            float mag = sqrtf(s);
            srinv[r] = (mag > 1e-6f) ? (1.0f / (mag + 1e-8f)) : 0.0f;
        }
    }
    __syncthreads();

    // ---------- Phase 3: fused coefficients cw[lp][k] ----------
    if (col < PC * WIN) {
        const int lp  = col / WIN;
        const int k   = col % WIN;
        const int pos = pos0 + lp;
        float c = 0.0f;
        const int w = (pos < WIN) ? pos : WIN;
        if (pos >= 1 && k < w) {
            const float ds = 0.1f * (1.0f + (float)(*layer_idx) * 0.8f);
            float Wk, wsum;
            if (w == 1) {
                Wk = expf(-1.0f);
                wsum = Wk;
            } else {
                const float dn = (float)(w - 1);
                wsum = 0.0f;
                for (int j = 0; j < w; ++j) wsum += expf(-(float)j / dn);
                Wk = expf(-(float)k / dn);
            }
            // diff used: global index pos-1-k -> register index lp + 5 - k
            c = Wk / (wsum + 1e-8f) * ds * srinv[lp + 5 - k];
        }
        scw[col] = c;
    }
    __syncthreads();

    // ---------- Phase 4: pure-register weighted sums, coalesced stores ----------
    {
        float* op = out + ((long long)(b * S_LEN + pos0)) * D_DIM + col;
        #pragma unroll
        for (int lp = 0; lp < PC; ++lp) {
            float acc = 0.0f;
            #pragma unroll
            for (int k = 0; k < WIN; ++k)
                acc = fmaf(scw[lp * WIN + k], diffs[lp + 5 - k], acc);
            op[lp * D_DIM] = acc;
        }
    }
}

extern "C" void kernel_launch(void* const* d_in, const int* in_sizes, int n_in,
                              void* d_out, int out_size) {
    const float* emb = (const float*)d_in[0];
    const int* layer_idx = (const int*)d_in[1];
    float* out = (float*)d_out;

    const int B = in_sizes[0] / (S_LEN * D_DIM);

    dim3 grid(S_LEN / PC, B);
    traj_flow_kernel<<<grid, D_DIM>>>(emb, layer_idx, out);
}